// round 10
// baseline (speedup 1.0000x reference)
#include <cuda_runtime.h>
#include <cuda_fp16.h>
#include <cstdint>

#define NN 100000
#define NE 1200000
#define D  64
#define SCAN_B 1024
#define NB ((NN + SCAN_B - 1) / SCAN_B)   // 98

// Scratch (device globals — no allocation allowed)
__device__ float              g_dis[NN];      // rsqrt(degree)
__device__ __half2            g_h[NN * D / 2];
__device__ unsigned long long g_pk64[NN];     // hi: count, lo: fixed-point wdeg
__device__ int                g_off[NN + 1];  // CSR offsets
__device__ int                g_cur[NN];      // fill cursors
__device__ unsigned long long g_state[NB];    // lookback: flag<<32 | value
__device__ int2               g_pack[NE];     // {src, bits(dis[src]*ew)}

// ---------------------------------------------------------------------------
__global__ void k_init() {
    int i = blockIdx.x * blockDim.x + threadIdx.x;
    if (i < NN) g_pk64[i] = 0ULL;
    if (i < NB) g_state[i] = 0ULL;
}

// one packed 64-bit atomic per edge: count + fixed-point weighted degree
__global__ void k_deg(const int* __restrict__ dst, const float* __restrict__ ew) {
    int e = blockIdx.x * blockDim.x + threadIdx.x;
    if (e < NE) {
        unsigned int q = __float2uint_rn(ew[e] * 16777216.0f);
        unsigned long long inc = (1ULL << 32) | (unsigned long long)q;
        atomicAdd(&g_pk64[dst[e]], inc);
    }
}

// ---------------------------------------------------------------------------
// Single-pass scan (decoupled lookback) + fused dis = rsqrt(deg).
// All NB=98 blocks are co-resident (<=148 SMs) so spinning is safe.
__global__ __launch_bounds__(SCAN_B) void k_scan() {
    __shared__ int wsum[32];
    __shared__ int s_base;
    const int bid  = blockIdx.x;
    const int i    = bid * SCAN_B + threadIdx.x;
    const int lane = threadIdx.x & 31, w = threadIdx.x >> 5;

    unsigned long long p = (i < NN) ? g_pk64[i] : 0ULL;
    int v = (int)(p >> 32);
    int s = v;
    #pragma unroll
    for (int d = 1; d < 32; d <<= 1) {
        int t = __shfl_up_sync(0xffffffffu, s, d);
        if (lane >= d) s += t;
    }
    if (lane == 31) wsum[w] = s;
    __syncthreads();
    if (w == 0) {
        int t = wsum[lane];
        #pragma unroll
        for (int d = 1; d < 32; d <<= 1) {
            int u = __shfl_up_sync(0xffffffffu, t, d);
            if (lane >= d) t += u;
        }
        wsum[lane] = t;
    }
    __syncthreads();
    const int wbase  = (w > 0) ? wsum[w - 1] : 0;
    const int excl   = s + wbase - v;       // block-local exclusive
    const int btotal = wsum[31];

    if (w == 0) {
        if (lane == 0) {
            unsigned long long st = (bid == 0)
                ? (2ULL << 32) | (unsigned int)btotal     // prefix (block 0)
                : (1ULL << 32) | (unsigned int)btotal;    // aggregate
            atomicExch(&g_state[bid], st);
        }
        int base = 0;
        if (bid > 0) {
            int j = bid - 1;
            while (true) {
                int idx = j - lane;                       // lane0 = nearest
                unsigned long long st = 0ULL;
                if (idx >= 0) {
                    do { st = *(volatile unsigned long long*)&g_state[idx]; }
                    while ((st >> 32) == 0ULL);
                }
                unsigned pf = __ballot_sync(0xffffffffu,
                                            idx >= 0 && (st >> 32) == 2ULL);
                int contrib; bool done;
                if (pf) {
                    int pl = __ffs(pf) - 1;               // nearest prefix
                    contrib = (lane <= pl) ? (int)(unsigned int)st : 0;
                    done = true;
                } else {
                    contrib = (idx >= 0) ? (int)(unsigned int)st : 0;
                    done = false;
                }
                #pragma unroll
                for (int d = 16; d; d >>= 1)
                    contrib += __shfl_down_sync(0xffffffffu, contrib, d);
                contrib = __shfl_sync(0xffffffffu, contrib, 0);
                base += contrib;
                if (done) break;
                j -= 32;
            }
            if (lane == 0)
                atomicExch(&g_state[bid],
                           (2ULL << 32) | (unsigned int)(base + btotal));
        }
        if (lane == 0) s_base = base;
    }
    __syncthreads();

    if (i < NN) {
        int o = excl + s_base;
        g_off[i] = o;
        g_cur[i] = o;
        float deg = 1.0f + (float)(unsigned int)p * (1.0f / 16777216.0f);
        g_dis[i] = rsqrtf(deg);
    }
    if (bid == NB - 1 && threadIdx.x == 0) g_off[NN] = NE;
}

// ---------------------------------------------------------------------------
// Fill CSR: pack {src, dis[src]*ew} into dst-grouped segments
__global__ void k_fill(const int* __restrict__ src, const int* __restrict__ dst,
                       const float* __restrict__ ew) {
    int e = blockIdx.x * blockDim.x + threadIdx.x;
    if (e >= NE) return;
    int s = src[e], d = dst[e];
    int pos = atomicAdd(&g_cur[d], 1);
    float m = g_dis[s] * ew[e];
    g_pack[pos] = make_int2(s, __float_as_int(m));
}

// ---------------------------------------------------------------------------
// HMMA GEMM, A direct-from-global: h = x @ W^T (fp16 in, f32 accum) -> g_h.
#define GROWS 128
#define XST 72
__global__ __launch_bounds__(256) void k_gemm(const float* __restrict__ x,
                                              const float* __restrict__ W) {
    __shared__ __half Ws[D * XST];

    const int tid  = threadIdx.x;
    const int lane = tid & 31;
    const int wid  = tid >> 5;
    const int base = blockIdx.x * GROWS;

    for (int t = tid; t < D * D; t += 256) {
        int j = t >> 6, k = t & 63;
        Ws[j * XST + k] = __float2half_rn(W[t]);
    }
    __syncthreads();

    uint32_t bfrag[8][4][2];
    {
        int n  = lane >> 2;
        int k0 = (lane & 3) << 1;
        #pragma unroll
        for (int nb = 0; nb < 8; nb++) {
            const __half* wp = &Ws[(nb * 8 + n) * XST];
            #pragma unroll
            for (int kc = 0; kc < 4; kc++) {
                bfrag[nb][kc][0] = *(const uint32_t*)&wp[kc * 16 + k0];
                bfrag[nb][kc][1] = *(const uint32_t*)&wp[kc * 16 + k0 + 8];
            }
        }
    }

    float acc[8][4];
    #pragma unroll
    for (int nb = 0; nb < 8; nb++)
        #pragma unroll
        for (int j = 0; j < 4; j++) acc[nb][j] = 0.f;

    const int gid = lane >> 2, tig = lane & 3;
    const int r0  = base + wid * 16 + gid;
    const int r1  = r0 + 8;
    const bool v0 = r0 < NN, v1 = r1 < NN;
    const float* xr0 = &x[(size_t)(v0 ? r0 : 0) * D + 2 * tig];
    const float* xr1 = &x[(size_t)(v1 ? r1 : 0) * D + 2 * tig];

    #pragma unroll
    for (int kc = 0; kc < 4; kc++) {
        float2 z = make_float2(0.f, 0.f);
        float2 f00 = v0 ? *(const float2*)&xr0[16 * kc]     : z;
        float2 f10 = v1 ? *(const float2*)&xr1[16 * kc]     : z;
        float2 f01 = v0 ? *(const float2*)&xr0[16 * kc + 8] : z;
        float2 f11 = v1 ? *(const float2*)&xr1[16 * kc + 8] : z;
        __half2 ha0 = __floats2half2_rn(f00.x, f00.y);
        __half2 ha1 = __floats2half2_rn(f10.x, f10.y);
        __half2 ha2 = __floats2half2_rn(f01.x, f01.y);
        __half2 ha3 = __floats2half2_rn(f11.x, f11.y);
        uint32_t a0 = *(uint32_t*)&ha0, a1 = *(uint32_t*)&ha1;
        uint32_t a2 = *(uint32_t*)&ha2, a3 = *(uint32_t*)&ha3;
        #pragma unroll
        for (int nb = 0; nb < 8; nb++) {
            asm volatile(
                "mma.sync.aligned.m16n8k16.row.col.f32.f16.f16.f32 "
                "{%0,%1,%2,%3}, {%4,%5,%6,%7}, {%8,%9}, {%0,%1,%2,%3};"
                : "+f"(acc[nb][0]), "+f"(acc[nb][1]),
                  "+f"(acc[nb][2]), "+f"(acc[nb][3])
                : "r"(a0), "r"(a1), "r"(a2), "r"(a3),
                  "r"(bfrag[nb][kc][0]), "r"(bfrag[nb][kc][1]));
        }
    }

    const int cc = tig << 1;
    #pragma unroll
    for (int nb = 0; nb < 8; nb++) {
        int c0 = nb * 8 + cc;
        if (v0) g_h[(r0 * D + c0) >> 1] = __floats2half2_rn(acc[nb][0], acc[nb][1]);
        if (v1) g_h[(r1 * D + c0) >> 1] = __floats2half2_rn(acc[nb][2], acc[nb][3]);
    }
}

// ---------------------------------------------------------------------------
// Aggregate (gather form): warp per dst node, unroll x8 for MLP.
// out[d] = relu( dis[d] * ( dis[d]*h[d] + sum_e m_e*h[src_e] ) + b )
__global__ __launch_bounds__(256) void k_aggr(const float* __restrict__ b,
                                              float* __restrict__ out) {
    int gw   = (blockIdx.x * 256 + threadIdx.x) >> 5;
    int lane = threadIdx.x & 31;
    if (gw >= NN) return;

    int off = g_off[gw];
    int end = g_off[gw + 1];
    float dd = g_dis[gw];

    float2 hd = __half22float2(g_h[gw * (D / 2) + lane]);
    float2 acc = make_float2(dd * hd.x, dd * hd.y);

    for (int eb = off; eb < end; eb += 32) {
        int n = min(32, end - eb);
        int2 pk = make_int2(0, 0);
        if (lane < n) pk = g_pack[eb + lane];
        int j = 0;
        for (; j + 8 <= n; j += 8) {
            int   ss[8]; float mm[8]; float2 ff[8];
            #pragma unroll
            for (int k = 0; k < 8; k++) {
                ss[k] = __shfl_sync(0xffffffffu, pk.x, j + k);
                mm[k] = __int_as_float(__shfl_sync(0xffffffffu, pk.y, j + k));
            }
            #pragma unroll
            for (int k = 0; k < 8; k++)
                ff[k] = __half22float2(g_h[ss[k] * (D / 2) + lane]);
            #pragma unroll
            for (int k = 0; k < 8; k++) {
                acc.x = fmaf(mm[k], ff[k].x, acc.x);
                acc.y = fmaf(mm[k], ff[k].y, acc.y);
            }
        }
        for (; j + 4 <= n; j += 4) {
            int   ss[4]; float mm[4]; float2 ff[4];
            #pragma unroll
            for (int k = 0; k < 4; k++) {
                ss[k] = __shfl_sync(0xffffffffu, pk.x, j + k);
                mm[k] = __int_as_float(__shfl_sync(0xffffffffu, pk.y, j + k));
            }
            #pragma unroll
            for (int k = 0; k < 4; k++)
                ff[k] = __half22float2(g_h[ss[k] * (D / 2) + lane]);
            #pragma unroll
            for (int k = 0; k < 4; k++) {
                acc.x = fmaf(mm[k], ff[k].x, acc.x);
                acc.y = fmaf(mm[k], ff[k].y, acc.y);
            }
        }
        for (; j < n; j++) {
            int   sj = __shfl_sync(0xffffffffu, pk.x, j);
            float mj = __int_as_float(__shfl_sync(0xffffffffu, pk.y, j));
            float2 f = __half22float2(g_h[sj * (D / 2) + lane]);
            acc.x = fmaf(mj, f.x, acc.x);
            acc.y = fmaf(mj, f.y, acc.y);
        }
    }

    float2 bb = *(const float2*)&b[2 * lane];
    float2 o;
    o.x = fmaxf(fmaf(dd, acc.x, bb.x), 0.f);
    o.y = fmaxf(fmaf(dd, acc.y, bb.y), 0.f);
    *(float2*)&out[gw * D + 2 * lane] = o;
}

// ---------------------------------------------------------------------------
extern "C" void kernel_launch(void* const* d_in, const int* in_sizes, int n_in,
                              void* d_out, int out_size) {
    const float* x  = (const float*)d_in[0];
    const int*   ei = (const int*)d_in[1];     // [2, NE] row-major
    const float* ea = (const float*)d_in[2];
    const float* W  = (const float*)d_in[3];
    const float* b  = (const float*)d_in[4];
    float* out = (float*)d_out;

    const int* src = ei;
    const int* dst = ei + NE;

    k_init<<<(NN + 255) / 256, 256>>>();
    k_deg<<<(NE + 255) / 256, 256>>>(dst, ea);
    k_scan<<<NB, SCAN_B>>>();                   // single-pass + fused rsqrt
    k_fill<<<(NE + 255) / 256, 256>>>(src, dst, ea);
    k_gemm<<<(NN + GROWS - 1) / GROWS, 256>>>(x, W);
    k_aggr<<<(NN * 32 + 255) / 256, 256>>>(b, out);
}

// round 12
// speedup vs baseline: 1.0383x; 1.0383x over previous
#include <cuda_runtime.h>
#include <cuda_fp16.h>
#include <cstdint>

#define NN 100000
#define NE 1200000
#define D  64
#define SCAN_B 1024
#define NB ((NN + SCAN_B - 1) / SCAN_B)   // 98

// Scratch (device globals — no allocation allowed)
__device__ float              g_dis[NN];      // rsqrt(degree)
__device__ __half2            g_h[NN * D / 2];
__device__ unsigned long long g_pk64[NN];     // hi: count, lo: fixed-point wdeg
__device__ int                g_off[NN + 1];  // CSR offsets
__device__ int                g_cur[NN];      // fill cursors
__device__ int                g_bsum[128];    // scan block sums
__device__ int2               g_pack[NE];     // {src, bits(dis[src]*ew)}

// ---------------------------------------------------------------------------
__global__ void k_init() {
    int i = blockIdx.x * blockDim.x + threadIdx.x;
    if (i < NN) g_pk64[i] = 0ULL;
}

// 4 edges/thread: packed 64-bit atomic (count + fixed-point weighted degree),
// 4 independent chains in flight.
__global__ void k_deg(const int* __restrict__ dst, const float* __restrict__ ew) {
    int t = blockIdx.x * blockDim.x + threadIdx.x;   // NE/4 threads
    int e = t << 2;
    if (e >= NE) return;
    int4   d4 = *(const int4*)&dst[e];
    float4 w4 = *(const float4*)&ew[e];
    unsigned long long i0 = (1ULL << 32) | __float2uint_rn(w4.x * 16777216.0f);
    unsigned long long i1 = (1ULL << 32) | __float2uint_rn(w4.y * 16777216.0f);
    unsigned long long i2 = (1ULL << 32) | __float2uint_rn(w4.z * 16777216.0f);
    unsigned long long i3 = (1ULL << 32) | __float2uint_rn(w4.w * 16777216.0f);
    atomicAdd(&g_pk64[d4.x], i0);
    atomicAdd(&g_pk64[d4.y], i1);
    atomicAdd(&g_pk64[d4.z], i2);
    atomicAdd(&g_pk64[d4.w], i3);
}

// ---------------------------------------------------------------------------
// Scan stage 1 (warp-shuffle over counts) + fused dis = rsqrt(deg).
__global__ void k_scan1() {
    __shared__ int wsum[32];
    int i = blockIdx.x * SCAN_B + threadIdx.x;
    int lane = threadIdx.x & 31, w = threadIdx.x >> 5;
    unsigned long long p = (i < NN) ? g_pk64[i] : 0ULL;
    int v = (int)(p >> 32);
    int s = v;
    #pragma unroll
    for (int d = 1; d < 32; d <<= 1) {
        int t = __shfl_up_sync(0xffffffffu, s, d);
        if (lane >= d) s += t;
    }
    if (lane == 31) wsum[w] = s;
    __syncthreads();
    if (w == 0) {
        int t = wsum[lane];
        #pragma unroll
        for (int d = 1; d < 32; d <<= 1) {
            int u = __shfl_up_sync(0xffffffffu, t, d);
            if (lane >= d) t += u;
        }
        wsum[lane] = t;
    }
    __syncthreads();
    int base = (w > 0) ? wsum[w - 1] : 0;
    int incl = s + base;
    if (i < NN) {
        g_off[i] = incl - v;               // exclusive, pre-blocksum
        float deg = 1.0f + (float)(unsigned int)p * (1.0f / 16777216.0f);
        g_dis[i] = rsqrtf(deg);
    }
    if (threadIdx.x == SCAN_B - 1) g_bsum[blockIdx.x] = incl;
}

// Scan stage 2+3 fused: each block redundantly scans the 98 block sums.
__global__ void k_scan3() {
    __shared__ int sbase[NB];
    if (threadIdx.x < 32) {
        int lane = threadIdx.x;
        int carry = 0;
        for (int c = 0; c < NB; c += 32) {
            int idx = c + lane;
            int v = (idx < NB) ? g_bsum[idx] : 0;
            int s = v;
            #pragma unroll
            for (int d = 1; d < 32; d <<= 1) {
                int t = __shfl_up_sync(0xffffffffu, s, d);
                if (lane >= d) s += t;
            }
            if (idx < NB) sbase[idx] = carry + s - v;
            carry += __shfl_sync(0xffffffffu, s, 31);
        }
    }
    __syncthreads();
    int i = blockIdx.x * SCAN_B + threadIdx.x;
    if (i < NN) {
        int o = g_off[i] + sbase[blockIdx.x];
        g_off[i] = o;
        g_cur[i] = o;
    }
    if (i == 0) g_off[NN] = NE;
}

// ---------------------------------------------------------------------------
// Fill CSR, 4 edges/thread: pack {src, dis[src]*ew} into dst-grouped segments.
// 4 independent gather->atomic->store chains for MLP.
__global__ void k_fill(const int* __restrict__ src, const int* __restrict__ dst,
                       const float* __restrict__ ew) {
    int t = blockIdx.x * blockDim.x + threadIdx.x;   // NE/4 threads
    int e = t << 2;
    if (e >= NE) return;
    int4   s4 = *(const int4*)&src[e];
    int4   d4 = *(const int4*)&dst[e];
    float4 w4 = *(const float4*)&ew[e];

    float m0 = g_dis[s4.x] * w4.x;
    float m1 = g_dis[s4.y] * w4.y;
    float m2 = g_dis[s4.z] * w4.z;
    float m3 = g_dis[s4.w] * w4.w;

    int p0 = atomicAdd(&g_cur[d4.x], 1);
    int p1 = atomicAdd(&g_cur[d4.y], 1);
    int p2 = atomicAdd(&g_cur[d4.z], 1);
    int p3 = atomicAdd(&g_cur[d4.w], 1);

    g_pack[p0] = make_int2(s4.x, __float_as_int(m0));
    g_pack[p1] = make_int2(s4.y, __float_as_int(m1));
    g_pack[p2] = make_int2(s4.z, __float_as_int(m2));
    g_pack[p3] = make_int2(s4.w, __float_as_int(m3));
}

// ---------------------------------------------------------------------------
// HMMA GEMM, A direct-from-global: h = x @ W^T (fp16 in, f32 accum) -> g_h.
#define GROWS 128
#define XST 72
__global__ __launch_bounds__(256) void k_gemm(const float* __restrict__ x,
                                              const float* __restrict__ W) {
    __shared__ __half Ws[D * XST];

    const int tid  = threadIdx.x;
    const int lane = tid & 31;
    const int wid  = tid >> 5;
    const int base = blockIdx.x * GROWS;

    for (int t = tid; t < D * D; t += 256) {
        int j = t >> 6, k = t & 63;
        Ws[j * XST + k] = __float2half_rn(W[t]);
    }
    __syncthreads();

    uint32_t bfrag[8][4][2];
    {
        int n  = lane >> 2;
        int k0 = (lane & 3) << 1;
        #pragma unroll
        for (int nb = 0; nb < 8; nb++) {
            const __half* wp = &Ws[(nb * 8 + n) * XST];
            #pragma unroll
            for (int kc = 0; kc < 4; kc++) {
                bfrag[nb][kc][0] = *(const uint32_t*)&wp[kc * 16 + k0];
                bfrag[nb][kc][1] = *(const uint32_t*)&wp[kc * 16 + k0 + 8];
            }
        }
    }

    float acc[8][4];
    #pragma unroll
    for (int nb = 0; nb < 8; nb++)
        #pragma unroll
        for (int j = 0; j < 4; j++) acc[nb][j] = 0.f;

    const int gid = lane >> 2, tig = lane & 3;
    const int r0  = base + wid * 16 + gid;
    const int r1  = r0 + 8;
    const bool v0 = r0 < NN, v1 = r1 < NN;
    const float* xr0 = &x[(size_t)(v0 ? r0 : 0) * D + 2 * tig];
    const float* xr1 = &x[(size_t)(v1 ? r1 : 0) * D + 2 * tig];

    #pragma unroll
    for (int kc = 0; kc < 4; kc++) {
        float2 z = make_float2(0.f, 0.f);
        float2 f00 = v0 ? *(const float2*)&xr0[16 * kc]     : z;
        float2 f10 = v1 ? *(const float2*)&xr1[16 * kc]     : z;
        float2 f01 = v0 ? *(const float2*)&xr0[16 * kc + 8] : z;
        float2 f11 = v1 ? *(const float2*)&xr1[16 * kc + 8] : z;
        __half2 ha0 = __floats2half2_rn(f00.x, f00.y);
        __half2 ha1 = __floats2half2_rn(f10.x, f10.y);
        __half2 ha2 = __floats2half2_rn(f01.x, f01.y);
        __half2 ha3 = __floats2half2_rn(f11.x, f11.y);
        uint32_t a0 = *(uint32_t*)&ha0, a1 = *(uint32_t*)&ha1;
        uint32_t a2 = *(uint32_t*)&ha2, a3 = *(uint32_t*)&ha3;
        #pragma unroll
        for (int nb = 0; nb < 8; nb++) {
            asm volatile(
                "mma.sync.aligned.m16n8k16.row.col.f32.f16.f16.f32 "
                "{%0,%1,%2,%3}, {%4,%5,%6,%7}, {%8,%9}, {%0,%1,%2,%3};"
                : "+f"(acc[nb][0]), "+f"(acc[nb][1]),
                  "+f"(acc[nb][2]), "+f"(acc[nb][3])
                : "r"(a0), "r"(a1), "r"(a2), "r"(a3),
                  "r"(bfrag[nb][kc][0]), "r"(bfrag[nb][kc][1]));
        }
    }

    const int cc = tig << 1;
    #pragma unroll
    for (int nb = 0; nb < 8; nb++) {
        int c0 = nb * 8 + cc;
        if (v0) g_h[(r0 * D + c0) >> 1] = __floats2half2_rn(acc[nb][0], acc[nb][1]);
        if (v1) g_h[(r1 * D + c0) >> 1] = __floats2half2_rn(acc[nb][2], acc[nb][3]);
    }
}

// ---------------------------------------------------------------------------
// Aggregate (gather form): warp per dst node, unroll x4 for MLP.
// out[d] = relu( dis[d] * ( dis[d]*h[d] + sum_e m_e*h[src_e] ) + b )
__global__ __launch_bounds__(256) void k_aggr(const float* __restrict__ b,
                                              float* __restrict__ out) {
    int gw   = (blockIdx.x * 256 + threadIdx.x) >> 5;
    int lane = threadIdx.x & 31;
    if (gw >= NN) return;

    int off = g_off[gw];
    int end = g_off[gw + 1];
    float dd = g_dis[gw];

    float2 hd = __half22float2(g_h[gw * (D / 2) + lane]);
    float2 acc = make_float2(dd * hd.x, dd * hd.y);

    for (int eb = off; eb < end; eb += 32) {
        int n = min(32, end - eb);
        int2 pk = make_int2(0, 0);
        if (lane < n) pk = g_pack[eb + lane];
        int j = 0;
        for (; j + 4 <= n; j += 4) {
            int   s0 = __shfl_sync(0xffffffffu, pk.x, j);
            int   s1 = __shfl_sync(0xffffffffu, pk.x, j + 1);
            int   s2 = __shfl_sync(0xffffffffu, pk.x, j + 2);
            int   s3 = __shfl_sync(0xffffffffu, pk.x, j + 3);
            float m0 = __int_as_float(__shfl_sync(0xffffffffu, pk.y, j));
            float m1 = __int_as_float(__shfl_sync(0xffffffffu, pk.y, j + 1));
            float m2 = __int_as_float(__shfl_sync(0xffffffffu, pk.y, j + 2));
            float m3 = __int_as_float(__shfl_sync(0xffffffffu, pk.y, j + 3));
            float2 f0 = __half22float2(g_h[s0 * (D / 2) + lane]);
            float2 f1 = __half22float2(g_h[s1 * (D / 2) + lane]);
            float2 f2 = __half22float2(g_h[s2 * (D / 2) + lane]);
            float2 f3 = __half22float2(g_h[s3 * (D / 2) + lane]);
            acc.x = fmaf(m0, f0.x, acc.x); acc.y = fmaf(m0, f0.y, acc.y);
            acc.x = fmaf(m1, f1.x, acc.x); acc.y = fmaf(m1, f1.y, acc.y);
            acc.x = fmaf(m2, f2.x, acc.x); acc.y = fmaf(m2, f2.y, acc.y);
            acc.x = fmaf(m3, f3.x, acc.x); acc.y = fmaf(m3, f3.y, acc.y);
        }
        for (; j < n; j++) {
            int   sj = __shfl_sync(0xffffffffu, pk.x, j);
            float mj = __int_as_float(__shfl_sync(0xffffffffu, pk.y, j));
            float2 f = __half22float2(g_h[sj * (D / 2) + lane]);
            acc.x = fmaf(mj, f.x, acc.x);
            acc.y = fmaf(mj, f.y, acc.y);
        }
    }

    float2 bb = *(const float2*)&b[2 * lane];
    float2 o;
    o.x = fmaxf(fmaf(dd, acc.x, bb.x), 0.f);
    o.y = fmaxf(fmaf(dd, acc.y, bb.y), 0.f);
    *(float2*)&out[gw * D + 2 * lane] = o;
}

// ---------------------------------------------------------------------------
extern "C" void kernel_launch(void* const* d_in, const int* in_sizes, int n_in,
                              void* d_out, int out_size) {
    const float* x  = (const float*)d_in[0];
    const int*   ei = (const int*)d_in[1];     // [2, NE] row-major
    const float* ea = (const float*)d_in[2];
    const float* W  = (const float*)d_in[3];
    const float* b  = (const float*)d_in[4];
    float* out = (float*)d_out;

    const int* src = ei;
    const int* dst = ei + NE;

    k_init<<<(NN + 255) / 256, 256>>>();
    k_deg<<<(NE / 4 + 255) / 256, 256>>>(dst, ea);
    k_scan1<<<NB, SCAN_B>>>();                  // + fused rsqrt
    k_scan3<<<NB, SCAN_B>>>();                  // scan2 fused in
    k_fill<<<(NE / 4 + 255) / 256, 256>>>(src, dst, ea);
    k_gemm<<<(NN + GROWS - 1) / GROWS, 256>>>(x, W);
    k_aggr<<<(NN * 32 + 255) / 256, 256>>>(b, out);
}

// round 13
// speedup vs baseline: 1.0472x; 1.0086x over previous
#include <cuda_runtime.h>
#include <cuda_fp16.h>
#include <cstdint>

#define NN 100000
#define NE 1200000
#define D  64
#define SCAN_B 1024
#define NB ((NN + SCAN_B - 1) / SCAN_B)   // 98

// Scratch (device globals — no allocation allowed; zero-initialized at load)
__device__ float              g_dis[NN];      // rsqrt(degree)
__device__ __half2            g_h[NN * D / 2];
__device__ unsigned long long g_pk64[NN];     // hi: count, lo: fixed-point wdeg
__device__ int                g_off[NN];      // segment start per node
__device__ int                g_cnt[NN];      // segment length per node
__device__ int                g_cur[NN];      // fill cursors
__device__ int                g_total;        // segment allocator (reset by k_gemm)
__device__ int2               g_pack[NE];     // {src, bits(ew)}

// ---------------------------------------------------------------------------
// one packed 64-bit atomic per edge: count + fixed-point weighted degree
__global__ void k_deg(const int* __restrict__ dst, const float* __restrict__ ew) {
    int e = blockIdx.x * blockDim.x + threadIdx.x;
    if (e < NE) {
        unsigned int q = __float2uint_rn(ew[e] * 16777216.0f);
        unsigned long long inc = (1ULL << 32) | (unsigned long long)q;
        atomicAdd(&g_pk64[dst[e]], inc);
    }
}

// ---------------------------------------------------------------------------
// Offsets in ONE kernel: block-local scan + one atomicAdd of the block total.
// Segment placement is arbitrary (block completion order) — valid because
// k_aggr reads {off, cnt}, never off[i+1]. Also resets g_pk64 for the next
// graph replay and computes dis = rsqrt(deg).
__global__ __launch_bounds__(SCAN_B) void k_offsets() {
    __shared__ int wsum[32];
    __shared__ int s_base;
    const int i    = blockIdx.x * SCAN_B + threadIdx.x;
    const int lane = threadIdx.x & 31, w = threadIdx.x >> 5;

    unsigned long long p = (i < NN) ? g_pk64[i] : 0ULL;
    if (i < NN) g_pk64[i] = 0ULL;           // clean slate for next replay
    int v = (int)(p >> 32);
    int s = v;
    #pragma unroll
    for (int d = 1; d < 32; d <<= 1) {
        int t = __shfl_up_sync(0xffffffffu, s, d);
        if (lane >= d) s += t;
    }
    if (lane == 31) wsum[w] = s;
    __syncthreads();
    if (w == 0) {
        int t = wsum[lane];
        #pragma unroll
        for (int d = 1; d < 32; d <<= 1) {
            int u = __shfl_up_sync(0xffffffffu, t, d);
            if (lane >= d) t += u;
        }
        wsum[lane] = t;
    }
    __syncthreads();
    const int excl   = s + ((w > 0) ? wsum[w - 1] : 0) - v;  // block-local excl
    const int btotal = wsum[31];
    if (threadIdx.x == 0) s_base = atomicAdd(&g_total, btotal);
    __syncthreads();

    if (i < NN) {
        int o = s_base + excl;
        g_off[i] = o;
        g_cur[i] = o;
        g_cnt[i] = v;
        float deg = 1.0f + (float)(unsigned int)p * (1.0f / 16777216.0f);
        g_dis[i] = rsqrtf(deg);
    }
}

// ---------------------------------------------------------------------------
// Fill CSR: pack raw {src, ew} (norm multiply deferred to k_aggr).
// Chain: coalesced loads -> atomic cursor -> scatter store.
__global__ void k_fill(const int* __restrict__ src, const int* __restrict__ dst,
                       const float* __restrict__ ew) {
    int e = blockIdx.x * blockDim.x + threadIdx.x;
    if (e >= NE) return;
    int pos = atomicAdd(&g_cur[dst[e]], 1);
    g_pack[pos] = make_int2(src[e], __float_as_int(ew[e]));
}

// ---------------------------------------------------------------------------
// HMMA GEMM, A direct-from-global: h = x @ W^T (fp16 in, f32 accum) -> g_h.
// Also resets g_total for the next graph replay.
#define GROWS 128
#define XST 72
__global__ __launch_bounds__(256) void k_gemm(const float* __restrict__ x,
                                              const float* __restrict__ W) {
    if (blockIdx.x == 0 && threadIdx.x == 0) g_total = 0;

    __shared__ __half Ws[D * XST];

    const int tid  = threadIdx.x;
    const int lane = tid & 31;
    const int wid  = tid >> 5;
    const int base = blockIdx.x * GROWS;

    for (int t = tid; t < D * D; t += 256) {
        int j = t >> 6, k = t & 63;
        Ws[j * XST + k] = __float2half_rn(W[t]);
    }
    __syncthreads();

    uint32_t bfrag[8][4][2];
    {
        int n  = lane >> 2;
        int k0 = (lane & 3) << 1;
        #pragma unroll
        for (int nb = 0; nb < 8; nb++) {
            const __half* wp = &Ws[(nb * 8 + n) * XST];
            #pragma unroll
            for (int kc = 0; kc < 4; kc++) {
                bfrag[nb][kc][0] = *(const uint32_t*)&wp[kc * 16 + k0];
                bfrag[nb][kc][1] = *(const uint32_t*)&wp[kc * 16 + k0 + 8];
            }
        }
    }

    float acc[8][4];
    #pragma unroll
    for (int nb = 0; nb < 8; nb++)
        #pragma unroll
        for (int j = 0; j < 4; j++) acc[nb][j] = 0.f;

    const int gid = lane >> 2, tig = lane & 3;
    const int r0  = base + wid * 16 + gid;
    const int r1  = r0 + 8;
    const bool v0 = r0 < NN, v1 = r1 < NN;
    const float* xr0 = &x[(size_t)(v0 ? r0 : 0) * D + 2 * tig];
    const float* xr1 = &x[(size_t)(v1 ? r1 : 0) * D + 2 * tig];

    #pragma unroll
    for (int kc = 0; kc < 4; kc++) {
        float2 z = make_float2(0.f, 0.f);
        float2 f00 = v0 ? *(const float2*)&xr0[16 * kc]     : z;
        float2 f10 = v1 ? *(const float2*)&xr1[16 * kc]     : z;
        float2 f01 = v0 ? *(const float2*)&xr0[16 * kc + 8] : z;
        float2 f11 = v1 ? *(const float2*)&xr1[16 * kc + 8] : z;
        __half2 ha0 = __floats2half2_rn(f00.x, f00.y);
        __half2 ha1 = __floats2half2_rn(f10.x, f10.y);
        __half2 ha2 = __floats2half2_rn(f01.x, f01.y);
        __half2 ha3 = __floats2half2_rn(f11.x, f11.y);
        uint32_t a0 = *(uint32_t*)&ha0, a1 = *(uint32_t*)&ha1;
        uint32_t a2 = *(uint32_t*)&ha2, a3 = *(uint32_t*)&ha3;
        #pragma unroll
        for (int nb = 0; nb < 8; nb++) {
            asm volatile(
                "mma.sync.aligned.m16n8k16.row.col.f32.f16.f16.f32 "
                "{%0,%1,%2,%3}, {%4,%5,%6,%7}, {%8,%9}, {%0,%1,%2,%3};"
                : "+f"(acc[nb][0]), "+f"(acc[nb][1]),
                  "+f"(acc[nb][2]), "+f"(acc[nb][3])
                : "r"(a0), "r"(a1), "r"(a2), "r"(a3),
                  "r"(bfrag[nb][kc][0]), "r"(bfrag[nb][kc][1]));
        }
    }

    const int cc = tig << 1;
    #pragma unroll
    for (int nb = 0; nb < 8; nb++) {
        int c0 = nb * 8 + cc;
        if (v0) g_h[(r0 * D + c0) >> 1] = __floats2half2_rn(acc[nb][0], acc[nb][1]);
        if (v1) g_h[(r1 * D + c0) >> 1] = __floats2half2_rn(acc[nb][2], acc[nb][3]);
    }
}

// ---------------------------------------------------------------------------
// Aggregate (gather form): warp per dst node, unroll x4 for MLP.
// norm m_e = dis[src]*ew computed here, 32-wide parallel during pack load.
// out[d] = relu( dis[d] * ( dis[d]*h[d] + sum_e m_e*h[src_e] ) + b )
__global__ __launch_bounds__(256) void k_aggr(const float* __restrict__ b,
                                              float* __restrict__ out) {
    int gw   = (blockIdx.x * 256 + threadIdx.x) >> 5;
    int lane = threadIdx.x & 31;
    if (gw >= NN) return;

    int off = g_off[gw];
    int end = off + g_cnt[gw];
    float dd = g_dis[gw];

    float2 hd = __half22float2(g_h[gw * (D / 2) + lane]);
    float2 acc = make_float2(dd * hd.x, dd * hd.y);

    for (int eb = off; eb < end; eb += 32) {
        int n = min(32, end - eb);
        int2  pk = make_int2(0, 0);
        float ml = 0.f;
        if (lane < n) {
            pk = g_pack[eb + lane];
            ml = g_dis[pk.x] * __int_as_float(pk.y);   // 32-wide random loads
        }
        int j = 0;
        for (; j + 4 <= n; j += 4) {
            int   s0 = __shfl_sync(0xffffffffu, pk.x, j);
            int   s1 = __shfl_sync(0xffffffffu, pk.x, j + 1);
            int   s2 = __shfl_sync(0xffffffffu, pk.x, j + 2);
            int   s3 = __shfl_sync(0xffffffffu, pk.x, j + 3);
            float m0 = __shfl_sync(0xffffffffu, ml, j);
            float m1 = __shfl_sync(0xffffffffu, ml, j + 1);
            float m2 = __shfl_sync(0xffffffffu, ml, j + 2);
            float m3 = __shfl_sync(0xffffffffu, ml, j + 3);
            float2 f0 = __half22float2(g_h[s0 * (D / 2) + lane]);
            float2 f1 = __half22float2(g_h[s1 * (D / 2) + lane]);
            float2 f2 = __half22float2(g_h[s2 * (D / 2) + lane]);
            float2 f3 = __half22float2(g_h[s3 * (D / 2) + lane]);
            acc.x = fmaf(m0, f0.x, acc.x); acc.y = fmaf(m0, f0.y, acc.y);
            acc.x = fmaf(m1, f1.x, acc.x); acc.y = fmaf(m1, f1.y, acc.y);
            acc.x = fmaf(m2, f2.x, acc.x); acc.y = fmaf(m2, f2.y, acc.y);
            acc.x = fmaf(m3, f3.x, acc.x); acc.y = fmaf(m3, f3.y, acc.y);
        }
        for (; j < n; j++) {
            int   sj = __shfl_sync(0xffffffffu, pk.x, j);
            float mj = __shfl_sync(0xffffffffu, ml, j);
            float2 f = __half22float2(g_h[sj * (D / 2) + lane]);
            acc.x = fmaf(mj, f.x, acc.x);
            acc.y = fmaf(mj, f.y, acc.y);
        }
    }

    float2 bb = *(const float2*)&b[2 * lane];
    float2 o;
    o.x = fmaxf(fmaf(dd, acc.x, bb.x), 0.f);
    o.y = fmaxf(fmaf(dd, acc.y, bb.y), 0.f);
    *(float2*)&out[gw * D + 2 * lane] = o;
}

// ---------------------------------------------------------------------------
extern "C" void kernel_launch(void* const* d_in, const int* in_sizes, int n_in,
                              void* d_out, int out_size) {
    const float* x  = (const float*)d_in[0];
    const int*   ei = (const int*)d_in[1];     // [2, NE] row-major
    const float* ea = (const float*)d_in[2];
    const float* W  = (const float*)d_in[3];
    const float* b  = (const float*)d_in[4];
    float* out = (float*)d_out;

    const int* src = ei;
    const int* dst = ei + NE;

    k_deg<<<(NE + 255) / 256, 256>>>(dst, ea);
    k_offsets<<<NB, SCAN_B>>>();               // scan + rsqrt + pk64 reset
    k_fill<<<(NE + 255) / 256, 256>>>(src, dst, ea);
    k_gemm<<<(NN + GROWS - 1) / GROWS, 256>>>(x, W);   // + g_total reset
    k_aggr<<<(NN * 32 + 255) / 256, 256>>>(b, out);
}

// round 14
// speedup vs baseline: 1.0932x; 1.0439x over previous
#include <cuda_runtime.h>
#include <cuda_fp16.h>
#include <cstdint>

#define NN 100000
#define NE 1200000
#define D  64
#define SCAN_B 1024
#define NB ((NN + SCAN_B - 1) / SCAN_B)   // 98

// Scratch (device globals — no allocation allowed; zero-initialized at load)
__device__ float              g_dis[NN];      // rsqrt(degree)
__device__ __half2            g_h[NN * D / 2];
__device__ unsigned long long g_pk64[NN];     // hi: count, lo: fixed-point wdeg
__device__ int                g_off[NN];      // segment start per node
__device__ int                g_cnt[NN];      // segment length per node
__device__ int                g_cur[NN];      // fill cursors
__device__ int                g_total;        // segment allocator (reset by k_gemm)
__device__ int2               g_pack[NE];     // {src, bits(dis[src]*ew)}

// ---------------------------------------------------------------------------
// one packed 64-bit atomic per edge: count + fixed-point weighted degree
__global__ void k_deg(const int* __restrict__ dst, const float* __restrict__ ew) {
    int e = blockIdx.x * blockDim.x + threadIdx.x;
    if (e < NE) {
        unsigned int q = __float2uint_rn(ew[e] * 16777216.0f);
        unsigned long long inc = (1ULL << 32) | (unsigned long long)q;
        atomicAdd(&g_pk64[dst[e]], inc);
    }
}

// ---------------------------------------------------------------------------
// Offsets in ONE kernel: block-local scan + one atomicAdd of the block total.
// Segment placement is arbitrary (block completion order) — valid because
// k_aggr reads {off, cnt}. Fuses dis = rsqrt(deg) and the g_pk64 reset.
__global__ __launch_bounds__(SCAN_B) void k_offsets() {
    __shared__ int wsum[32];
    __shared__ int s_base;
    const int i    = blockIdx.x * SCAN_B + threadIdx.x;
    const int lane = threadIdx.x & 31, w = threadIdx.x >> 5;

    unsigned long long p = (i < NN) ? g_pk64[i] : 0ULL;
    if (i < NN) g_pk64[i] = 0ULL;           // clean slate for next replay
    int v = (int)(p >> 32);
    int s = v;
    #pragma unroll
    for (int d = 1; d < 32; d <<= 1) {
        int t = __shfl_up_sync(0xffffffffu, s, d);
        if (lane >= d) s += t;
    }
    if (lane == 31) wsum[w] = s;
    __syncthreads();
    if (w == 0) {
        int t = wsum[lane];
        #pragma unroll
        for (int d = 1; d < 32; d <<= 1) {
            int u = __shfl_up_sync(0xffffffffu, t, d);
            if (lane >= d) t += u;
        }
        wsum[lane] = t;
    }
    __syncthreads();
    const int excl   = s + ((w > 0) ? wsum[w - 1] : 0) - v;  // block-local excl
    const int btotal = wsum[31];
    if (threadIdx.x == 0) s_base = atomicAdd(&g_total, btotal);
    __syncthreads();

    if (i < NN) {
        int o = s_base + excl;
        g_off[i] = o;
        g_cur[i] = o;
        g_cnt[i] = v;
        float deg = 1.0f + (float)(unsigned int)p * (1.0f / 16777216.0f);
        g_dis[i] = rsqrtf(deg);
    }
}

// ---------------------------------------------------------------------------
// Fill CSR: pack {src, dis[src]*ew} (norm computed HERE — k_aggr stays lean).
__global__ void k_fill(const int* __restrict__ src, const int* __restrict__ dst,
                       const float* __restrict__ ew) {
    int e = blockIdx.x * blockDim.x + threadIdx.x;
    if (e >= NE) return;
    int s = src[e], d = dst[e];
    int pos = atomicAdd(&g_cur[d], 1);
    float m = g_dis[s] * ew[e];
    g_pack[pos] = make_int2(s, __float_as_int(m));
}

// ---------------------------------------------------------------------------
// HMMA GEMM, A direct-from-global: h = x @ W^T (fp16 in, f32 accum) -> g_h.
// Also resets g_total for the next graph replay.
#define GROWS 128
#define XST 72
__global__ __launch_bounds__(256) void k_gemm(const float* __restrict__ x,
                                              const float* __restrict__ W) {
    if (blockIdx.x == 0 && threadIdx.x == 0) g_total = 0;

    __shared__ __half Ws[D * XST];

    const int tid  = threadIdx.x;
    const int lane = tid & 31;
    const int wid  = tid >> 5;
    const int base = blockIdx.x * GROWS;

    for (int t = tid; t < D * D; t += 256) {
        int j = t >> 6, k = t & 63;
        Ws[j * XST + k] = __float2half_rn(W[t]);
    }
    __syncthreads();

    uint32_t bfrag[8][4][2];
    {
        int n  = lane >> 2;
        int k0 = (lane & 3) << 1;
        #pragma unroll
        for (int nb = 0; nb < 8; nb++) {
            const __half* wp = &Ws[(nb * 8 + n) * XST];
            #pragma unroll
            for (int kc = 0; kc < 4; kc++) {
                bfrag[nb][kc][0] = *(const uint32_t*)&wp[kc * 16 + k0];
                bfrag[nb][kc][1] = *(const uint32_t*)&wp[kc * 16 + k0 + 8];
            }
        }
    }

    float acc[8][4];
    #pragma unroll
    for (int nb = 0; nb < 8; nb++)
        #pragma unroll
        for (int j = 0; j < 4; j++) acc[nb][j] = 0.f;

    const int gid = lane >> 2, tig = lane & 3;
    const int r0  = base + wid * 16 + gid;
    const int r1  = r0 + 8;
    const bool v0 = r0 < NN, v1 = r1 < NN;
    const float* xr0 = &x[(size_t)(v0 ? r0 : 0) * D + 2 * tig];
    const float* xr1 = &x[(size_t)(v1 ? r1 : 0) * D + 2 * tig];

    #pragma unroll
    for (int kc = 0; kc < 4; kc++) {
        float2 z = make_float2(0.f, 0.f);
        float2 f00 = v0 ? *(const float2*)&xr0[16 * kc]     : z;
        float2 f10 = v1 ? *(const float2*)&xr1[16 * kc]     : z;
        float2 f01 = v0 ? *(const float2*)&xr0[16 * kc + 8] : z;
        float2 f11 = v1 ? *(const float2*)&xr1[16 * kc + 8] : z;
        __half2 ha0 = __floats2half2_rn(f00.x, f00.y);
        __half2 ha1 = __floats2half2_rn(f10.x, f10.y);
        __half2 ha2 = __floats2half2_rn(f01.x, f01.y);
        __half2 ha3 = __floats2half2_rn(f11.x, f11.y);
        uint32_t a0 = *(uint32_t*)&ha0, a1 = *(uint32_t*)&ha1;
        uint32_t a2 = *(uint32_t*)&ha2, a3 = *(uint32_t*)&ha3;
        #pragma unroll
        for (int nb = 0; nb < 8; nb++) {
            asm volatile(
                "mma.sync.aligned.m16n8k16.row.col.f32.f16.f16.f32 "
                "{%0,%1,%2,%3}, {%4,%5,%6,%7}, {%8,%9}, {%0,%1,%2,%3};"
                : "+f"(acc[nb][0]), "+f"(acc[nb][1]),
                  "+f"(acc[nb][2]), "+f"(acc[nb][3])
                : "r"(a0), "r"(a1), "r"(a2), "r"(a3),
                  "r"(bfrag[nb][kc][0]), "r"(bfrag[nb][kc][1]));
        }
    }

    const int cc = tig << 1;
    #pragma unroll
    for (int nb = 0; nb < 8; nb++) {
        int c0 = nb * 8 + cc;
        if (v0) g_h[(r0 * D + c0) >> 1] = __floats2half2_rn(acc[nb][0], acc[nb][1]);
        if (v1) g_h[(r1 * D + c0) >> 1] = __floats2half2_rn(acc[nb][2], acc[nb][3]);
    }
}

// ---------------------------------------------------------------------------
// Aggregate (gather form): warp per dst node, unroll x4 for MLP.
// out[d] = relu( dis[d] * ( dis[d]*h[d] + sum_e m_e*h[src_e] ) + b )
__global__ __launch_bounds__(256) void k_aggr(const float* __restrict__ b,
                                              float* __restrict__ out) {
    int gw   = (blockIdx.x * 256 + threadIdx.x) >> 5;
    int lane = threadIdx.x & 31;
    if (gw >= NN) return;

    int off = g_off[gw];
    int end = off + g_cnt[gw];
    float dd = g_dis[gw];

    float2 hd = __half22float2(g_h[gw * (D / 2) + lane]);
    float2 acc = make_float2(dd * hd.x, dd * hd.y);

    for (int eb = off; eb < end; eb += 32) {
        int n = min(32, end - eb);
        int2 pk = make_int2(0, 0);
        if (lane < n) pk = g_pack[eb + lane];
        int j = 0;
        for (; j + 4 <= n; j += 4) {
            int   s0 = __shfl_sync(0xffffffffu, pk.x, j);
            int   s1 = __shfl_sync(0xffffffffu, pk.x, j + 1);
            int   s2 = __shfl_sync(0xffffffffu, pk.x, j + 2);
            int   s3 = __shfl_sync(0xffffffffu, pk.x, j + 3);
            float m0 = __int_as_float(__shfl_sync(0xffffffffu, pk.y, j));
            float m1 = __int_as_float(__shfl_sync(0xffffffffu, pk.y, j + 1));
            float m2 = __int_as_float(__shfl_sync(0xffffffffu, pk.y, j + 2));
            float m3 = __int_as_float(__shfl_sync(0xffffffffu, pk.y, j + 3));
            float2 f0 = __half22float2(g_h[s0 * (D / 2) + lane]);
            float2 f1 = __half22float2(g_h[s1 * (D / 2) + lane]);
            float2 f2 = __half22float2(g_h[s2 * (D / 2) + lane]);
            float2 f3 = __half22float2(g_h[s3 * (D / 2) + lane]);
            acc.x = fmaf(m0, f0.x, acc.x); acc.y = fmaf(m0, f0.y, acc.y);
            acc.x = fmaf(m1, f1.x, acc.x); acc.y = fmaf(m1, f1.y, acc.y);
            acc.x = fmaf(m2, f2.x, acc.x); acc.y = fmaf(m2, f2.y, acc.y);
            acc.x = fmaf(m3, f3.x, acc.x); acc.y = fmaf(m3, f3.y, acc.y);
        }
        for (; j < n; j++) {
            int   sj = __shfl_sync(0xffffffffu, pk.x, j);
            float mj = __int_as_float(__shfl_sync(0xffffffffu, pk.y, j));
            float2 f = __half22float2(g_h[sj * (D / 2) + lane]);
            acc.x = fmaf(mj, f.x, acc.x);
            acc.y = fmaf(mj, f.y, acc.y);
        }
    }

    float2 bb = *(const float2*)&b[2 * lane];
    float2 o;
    o.x = fmaxf(fmaf(dd, acc.x, bb.x), 0.f);
    o.y = fmaxf(fmaf(dd, acc.y, bb.y), 0.f);
    *(float2*)&out[gw * D + 2 * lane] = o;
}

// ---------------------------------------------------------------------------
extern "C" void kernel_launch(void* const* d_in, const int* in_sizes, int n_in,
                              void* d_out, int out_size) {
    const float* x  = (const float*)d_in[0];
    const int*   ei = (const int*)d_in[1];     // [2, NE] row-major
    const float* ea = (const float*)d_in[2];
    const float* W  = (const float*)d_in[3];
    const float* b  = (const float*)d_in[4];
    float* out = (float*)d_out;

    const int* src = ei;
    const int* dst = ei + NE;

    k_deg<<<(NE + 255) / 256, 256>>>(dst, ea);
    k_offsets<<<NB, SCAN_B>>>();               // scan + rsqrt + pk64 reset
    k_fill<<<(NE + 255) / 256, 256>>>(src, dst, ea);
    k_gemm<<<(NN + GROWS - 1) / GROWS, 256>>>(x, W);   // + g_total reset
    k_aggr<<<(NN * 32 + 255) / 256, 256>>>(b, out);
}